// round 12
// baseline (speedup 1.0000x reference)
#include <cuda_runtime.h>
#include <cstdint>

// GNNLandmarkHead fused per-(b,t) CTA, tf32 mma.sync.m16n8k8 (base ISA).
// A (agg) kept ROW-MAJOR in SMEM, fragments loaded via ldmatrix.m8n8.b16
// (16B rows of 4xf32 give exactly the tf32 fragment mapping). B = W^T staged
// row-major(n) once per layer, fragments via ldmatrix.x2. cvt.rna post-load.
// Warp split ng=2 x mg=4: nh=wp&1 owns 32 features; mgp=wp>>1 owns m-tiles
// {0,1}/{2}/{3}/{4}. M padded to 80; ldmatrix rows >=68 clamped to row 0
// (garbage, discarded). Pitch 68 floats everywhere -> conflict-free ldmatrix.

#define B_  32
#define T_  256
#define N_  68
#define F_  64
#define HP  68
#define THREADS 256
#define NLAYERS 3
#define ROWB 272          // 68 floats * 4B

// SMEM byte offsets (16B aligned)
#define SM_MUSIG 0        // 68 float2 = 544
#define SM_PART  544      // 68 x 2 float2 = 1088
#define SM_POOL  1632     // 64 f32 = 256 (+pad)
#define SM_AGG   1920     // 68 x 68 f32 = 18496
#define SM_WT    20416    // 64 x 68 f32 = 17408
#define SM_H     37824    // 68 x 68 f32 = 18496
#define SM_TOTAL 56320

static __device__ __forceinline__ uint32_t s2u(const void* p) {
    uint32_t a;
    asm("{ .reg .u64 t; cvta.to.shared.u64 t, %1; cvt.u32.u64 %0, t; }"
        : "=r"(a) : "l"(p));
    return a;
}
static __device__ __forceinline__ uint32_t f2tf32(float f) {
    uint32_t u;
    asm("cvt.rna.tf32.f32 %0, %1;" : "=r"(u) : "f"(f));
    return u;
}
static __device__ __forceinline__ uint32_t cvt_u(uint32_t raw) {
    return f2tf32(__uint_as_float(raw));
}
static __device__ __forceinline__ void ldmx4(uint32_t* r, uint32_t addr) {
    asm volatile("ldmatrix.sync.aligned.m8n8.x4.shared.b16 {%0,%1,%2,%3}, [%4];"
        : "=r"(r[0]), "=r"(r[1]), "=r"(r[2]), "=r"(r[3]) : "r"(addr));
}
static __device__ __forceinline__ void ldmx2(uint32_t* r, uint32_t addr) {
    asm volatile("ldmatrix.sync.aligned.m8n8.x2.shared.b16 {%0,%1}, [%2];"
        : "=r"(r[0]), "=r"(r[1]) : "r"(addr));
}
static __device__ __forceinline__ void mma_tf32(float* d, const uint32_t* a,
                                                const uint32_t* b) {
    asm volatile(
        "mma.sync.aligned.m16n8k8.row.col.f32.tf32.tf32.f32 "
        "{%0,%1,%2,%3}, {%4,%5,%6,%7}, {%8,%9}, {%0,%1,%2,%3};"
        : "+f"(d[0]), "+f"(d[1]), "+f"(d[2]), "+f"(d[3])
        : "r"(a[0]), "r"(a[1]), "r"(a[2]), "r"(a[3]), "r"(b[0]), "r"(b[1]));
}

__global__ void zero_out_kernel(float* out) {
    if (threadIdx.x < B_) out[threadIdx.x] = 0.0f;
}

__global__ __launch_bounds__(THREADS, 3)
void gnn_landmark_kernel(
    const float* __restrict__ x,       // (B,T,N,2)
    const float* __restrict__ W_enc,   // (2,F)
    const float* __restrict__ b_enc,   // (F)
    const float* __restrict__ W_gnn,   // (L,F,F)
    const float* __restrict__ b_gnn,   // (L,F)
    const float* __restrict__ gamma_,  // (L,F)
    const float* __restrict__ beta_,   // (L,F)
    const float* __restrict__ W1,      // (F,32)
    const float* __restrict__ b1,      // (32)
    const float* __restrict__ W2,      // (32,1)
    const float* __restrict__ b2,      // (1)
    float* __restrict__ out)           // (B)
{
    extern __shared__ char smc[];
    const uint32_t sb = s2u(smc);
    float* sh_h    = (float*)(smc + SM_H);
    float* sh_agg  = (float*)(smc + SM_AGG);
    float* sh_wt   = (float*)(smc + SM_WT);
    float* sh_pool = (float*)(smc + SM_POOL);
    float2* part   = (float2*)(smc + SM_PART);
    float2* musig  = (float2*)(smc + SM_MUSIG);

    const int tid  = threadIdx.x;
    const int lane = tid & 31;
    const int wp   = tid >> 5;
    const int nh   = wp & 1;              // feature half (32 cols)
    const int mgp  = wp >> 1;             // m-group 0..3
    const int mtb  = (mgp == 0) ? 0 : (mgp + 1);  // {0,1},{2},{3},{4}
    const int mtn  = (mgp == 0) ? 2 : 1;
    const int g    = lane >> 2;
    const int t    = lane & 3;

    // ---- encoder: h = x @ W_enc + b_enc
    const float* xb = x + (size_t)blockIdx.x * (N_ * 2);
    for (int idx = tid; idx < N_ * 16; idx += THREADS) {
        int n  = idx >> 4;
        int f4 = (idx & 15) << 2;
        float x0 = xb[2 * n];
        float x1 = xb[2 * n + 1];
        float4 w0 = __ldg((const float4*)(W_enc + f4));
        float4 w1 = __ldg((const float4*)(W_enc + F_ + f4));
        float4 be = __ldg((const float4*)(b_enc + f4));
        float4 h;
        h.x = fmaf(x0, w0.x, fmaf(x1, w1.x, be.x));
        h.y = fmaf(x0, w0.y, fmaf(x1, w1.y, be.y));
        h.z = fmaf(x0, w0.z, fmaf(x1, w1.z, be.z));
        h.w = fmaf(x0, w0.w, fmaf(x1, w1.w, be.w));
        *(float4*)(sh_h + n * HP + f4) = h;
    }
    __syncthreads();

    // ---- constant lane address bases (recomputed cheaply; layer-invariant)
    uint32_t aAddr[2];
    #pragma unroll
    for (int i = 0; i < 2; ++i) {
        int mt  = mtb + i;
        int row = mt * 16 + ((lane >> 3) & 1) * 8 + (lane & 7);
        if (row >= N_) row = 0;                 // clamp: garbage rows
        aAddr[i] = sb + SM_AGG + (uint32_t)(row * ROWB + ((lane >> 4) & 1) * 16);
    }
    uint32_t bAddr[4];
    {
        int l4 = lane & 15;
        #pragma unroll
        for (int nt = 0; nt < 4; ++nt) {
            int n = nh * 32 + nt * 8 + (l4 & 7);
            bAddr[nt] = sb + SM_WT + (uint32_t)(n * ROWB + ((l4 >> 3) & 1) * 16);
        }
    }

    for (int l = 0; l < NLAYERS; ++l) {
        const float* Wl = W_gnn + l * (F_ * F_);

        // ---- stage W^T (rows = n, cols = k), raw f32
        {
            int k = tid & 63, q = tid >> 6;       // q: 0..3 -> n block 16q
            const float* wr = Wl + k * F_ + q * 16;
            #pragma unroll
            for (int c = 0; c < 4; ++c) {
                float4 v = __ldg((const float4*)(wr + 4 * c));
                int n = q * 16 + 4 * c;
                sh_wt[(n + 0) * HP + k] = v.x;
                sh_wt[(n + 1) * HP + k] = v.y;
                sh_wt[(n + 2) * HP + k] = v.z;
                sh_wt[(n + 3) * HP + k] = v.w;
            }
        }
        // ---- stage agg row-major via 5-row strips (neighbor-load reuse)
        {
            int s = tid & 15, j = (tid >> 4) << 2;   // strip, float4 col
            float4 v[7];
            #pragma unroll
            for (int o = 0; o < 7; ++o) {
                int r = 5 * s - 1 + o;
                v[o] = ((unsigned)r < N_) ? *(const float4*)(sh_h + r * HP + j)
                                          : make_float4(0.f, 0.f, 0.f, 0.f);
            }
            #pragma unroll
            for (int o = 0; o < 5; ++o) {
                int r = 5 * s + o;
                if (r < N_) {
                    float4 a;
                    a.x = v[o].x + v[o + 2].x;
                    a.y = v[o].y + v[o + 2].y;
                    a.z = v[o].z + v[o + 2].z;
                    a.w = v[o].w + v[o + 2].w;
                    *(float4*)(sh_agg + r * HP + j) = a;
                }
            }
        }
        __syncthreads();

        // ---- warp GEMM: ldmatrix A (row-major agg) + ldmatrix B (W^T rows)
        float acc[2][4][4];
        #pragma unroll
        for (int i = 0; i < 2; ++i)
            #pragma unroll
            for (int nt = 0; nt < 4; ++nt)
                #pragma unroll
                for (int q = 0; q < 4; ++q) acc[i][nt][q] = 0.f;

        #pragma unroll
        for (int ks = 0; ks < 8; ++ks) {
            const uint32_t koff = (uint32_t)(ks * 32);
            uint32_t b[4][2];
            #pragma unroll
            for (int nt = 0; nt < 4; ++nt) {
                ldmx2(b[nt], bAddr[nt] + koff);
                b[nt][0] = cvt_u(b[nt][0]);
                b[nt][1] = cvt_u(b[nt][1]);
            }
            #pragma unroll
            for (int i = 0; i < 2; ++i) {
                if (i < mtn) {
                    uint32_t a[4];
                    ldmx4(a, aAddr[i] + koff);
                    a[0] = cvt_u(a[0]); a[1] = cvt_u(a[1]);
                    a[2] = cvt_u(a[2]); a[3] = cvt_u(a[3]);
                    #pragma unroll
                    for (int nt = 0; nt < 4; ++nt)
                        mma_tf32(acc[i][nt], a, b[nt]);
                }
            }
        }

        // ---- epilogue: bias+relu, LN partials (32-col per warp), reduce, apply
        float2 bias[4];
        #pragma unroll
        for (int nt = 0; nt < 4; ++nt)
            bias[nt] = __ldg((const float2*)(b_gnn + l * F_ + nh * 32 + nt * 8 + 2 * t));

        #pragma unroll
        for (int i = 0; i < 2; ++i) {
            if (i < mtn) {
                int r0 = (mtb + i) * 16 + g;
                int r1 = r0 + 8;
                float s1a = 0.f, s2a = 0.f, s1b = 0.f, s2b = 0.f;
                #pragma unroll
                for (int nt = 0; nt < 4; ++nt) {
                    float z0 = fmaxf(acc[i][nt][0] + bias[nt].x, 0.f);
                    float z1 = fmaxf(acc[i][nt][1] + bias[nt].y, 0.f);
                    float z2 = fmaxf(acc[i][nt][2] + bias[nt].x, 0.f);
                    float z3 = fmaxf(acc[i][nt][3] + bias[nt].y, 0.f);
                    s1a += z0 + z1;  s2a += fmaf(z0, z0, z1 * z1);
                    s1b += z2 + z3;  s2b += fmaf(z2, z2, z3 * z3);
                }
                #pragma unroll
                for (int off = 1; off < 4; off <<= 1) {
                    s1a += __shfl_xor_sync(0xffffffffu, s1a, off);
                    s2a += __shfl_xor_sync(0xffffffffu, s2a, off);
                    s1b += __shfl_xor_sync(0xffffffffu, s1b, off);
                    s2b += __shfl_xor_sync(0xffffffffu, s2b, off);
                }
                if (t == 0) {
                    if (r0 < N_) part[r0 * 2 + nh] = make_float2(s1a, s2a);
                    if (r1 < N_) part[r1 * 2 + nh] = make_float2(s1b, s2b);
                }
            }
        }
        __syncthreads();

        if (tid < N_) {
            float2 p0 = part[tid * 2 + 0];
            float2 p1 = part[tid * 2 + 1];
            float s1 = p0.x + p1.x;
            float s2 = p0.y + p1.y;
            float mu  = s1 * (1.0f / F_);
            float var = s2 * (1.0f / F_) - mu * mu;
            musig[tid] = make_float2(mu, rsqrtf(var + 1e-5f));
        }
        __syncthreads();

        float2 gm[4], bt[4];
        #pragma unroll
        for (int nt = 0; nt < 4; ++nt) {
            int c = nh * 32 + nt * 8 + 2 * t;
            gm[nt] = __ldg((const float2*)(gamma_ + l * F_ + c));
            bt[nt] = __ldg((const float2*)(beta_ + l * F_ + c));
        }

        #pragma unroll
        for (int i = 0; i < 2; ++i) {
            if (i < mtn) {
                int r0 = (mtb + i) * 16 + g;
                int r1 = r0 + 8;
                if (r0 < N_) {
                    float2 ms = musig[r0];
                    #pragma unroll
                    for (int nt = 0; nt < 4; ++nt) {
                        int c = nh * 32 + nt * 8 + 2 * t;
                        float z0 = fmaxf(acc[i][nt][0] + bias[nt].x, 0.f);
                        float z1 = fmaxf(acc[i][nt][1] + bias[nt].y, 0.f);
                        float2* hp = (float2*)(sh_h + r0 * HP + c);
                        float2 h = *hp;
                        h.x += fmaf((z0 - ms.x) * ms.y, gm[nt].x, bt[nt].x);
                        h.y += fmaf((z1 - ms.x) * ms.y, gm[nt].y, bt[nt].y);
                        *hp = h;
                    }
                }
                if (r1 < N_) {
                    float2 ms = musig[r1];
                    #pragma unroll
                    for (int nt = 0; nt < 4; ++nt) {
                        int c = nh * 32 + nt * 8 + 2 * t;
                        float z2 = fmaxf(acc[i][nt][2] + bias[nt].x, 0.f);
                        float z3 = fmaxf(acc[i][nt][3] + bias[nt].y, 0.f);
                        float2* hp = (float2*)(sh_h + r1 * HP + c);
                        float2 h = *hp;
                        h.x += fmaf((z2 - ms.x) * ms.y, gm[nt].x, bt[nt].x);
                        h.y += fmaf((z3 - ms.x) * ms.y, gm[nt].y, bt[nt].y);
                        *hp = h;
                    }
                }
            }
        }
        __syncthreads();
    }

    // ---- pool over nodes ----
    if (tid < F_) {
        float s = 0.f;
        #pragma unroll
        for (int n = 0; n < N_; ++n) s += sh_h[n * HP + tid];
        sh_pool[tid] = s * (1.0f / N_);
    }
    __syncthreads();

    // ---- MLP head + mean over T ----
    if (tid < 32) {
        float a = __ldg(b1 + tid);
        #pragma unroll
        for (int f = 0; f < F_; ++f)
            a = fmaf(sh_pool[f], __ldg(W1 + f * 32 + tid), a);
        a = fmaxf(a, 0.f) * __ldg(W2 + tid);
        #pragma unroll
        for (int off = 16; off > 0; off >>= 1)
            a += __shfl_xor_sync(0xffffffffu, a, off);
        if (tid == 0) {
            float logit = a + __ldg(b2);
            atomicAdd(out + (blockIdx.x >> 8), logit * (1.0f / T_));
        }
    }
}

extern "C" void kernel_launch(void* const* d_in, const int* in_sizes, int n_in,
                              void* d_out, int out_size) {
    const float* x      = (const float*)d_in[0];   // landmarks_sequence
    // d_in[1] = adj (tridiagonal; structure hardcoded)
    const float* W_enc  = (const float*)d_in[2];
    const float* b_enc  = (const float*)d_in[3];
    const float* W_gnn  = (const float*)d_in[4];
    const float* b_gnn  = (const float*)d_in[5];
    const float* gamma_ = (const float*)d_in[6];
    const float* beta_  = (const float*)d_in[7];
    const float* W1     = (const float*)d_in[8];
    const float* b1     = (const float*)d_in[9];
    const float* W2     = (const float*)d_in[10];
    const float* b2     = (const float*)d_in[11];
    float* out = (float*)d_out;

    cudaFuncSetAttribute(gnn_landmark_kernel,
                         cudaFuncAttributeMaxDynamicSharedMemorySize, SM_TOTAL);

    zero_out_kernel<<<1, 32>>>(out);
    gnn_landmark_kernel<<<B_ * T_, THREADS, SM_TOTAL>>>(
        x, W_enc, b_enc, W_gnn, b_gnn, gamma_, beta_, W1, b1, W2, b2, out);
}

// round 15
// speedup vs baseline: 1.0392x; 1.0392x over previous
#include <cuda_runtime.h>
#include <cstdint>

// GNNLandmarkHead fused per-(b,t) CTA, tf32 mma.sync.m16n8k8 (base ISA).
// agg and W^T are stored in SMEM ALREADY tf32-rounded (cvt.rna at staging,
// output is a valid f32 bit pattern) -> ldmatrix feeds MMA directly, zero cvt
// in the GEMM loop. A row-major via ldmatrix.x4 (16B rows of 4xf32 = exact
// tf32 fragment map); B = W^T rows via ldmatrix.x2.
// Warp split ng=2 x mg=4: nh=wp&1 owns 32 features; mgp=wp>>1 owns m-tiles
// {0,1}/{2}/{3}/{4}. M padded to 80; ldmatrix rows >=68 clamped to row 0
// (garbage, discarded). Pitch 68 floats -> conflict-free ldmatrix.

#define B_  32
#define T_  256
#define N_  68
#define F_  64
#define HP  68
#define THREADS 256
#define NLAYERS 3
#define ROWB 272          // 68 floats * 4B

// SMEM byte offsets (16B aligned)
#define SM_MUSIG 0        // 68 float2 = 544
#define SM_PART  544      // 68 x 2 float2 = 1088
#define SM_POOL  1632     // 64 f32 = 256 (+pad)
#define SM_AGG   1920     // 68 x 68 f32 = 18496
#define SM_WT    20416    // 64 x 68 f32 = 17408
#define SM_H     37824    // 68 x 68 f32 = 18496
#define SM_TOTAL 56320

static __device__ __forceinline__ uint32_t s2u(const void* p) {
    uint32_t a;
    asm("{ .reg .u64 t; cvta.to.shared.u64 t, %1; cvt.u32.u64 %0, t; }"
        : "=r"(a) : "l"(p));
    return a;
}
static __device__ __forceinline__ float f2tf32f(float f) {
    uint32_t u;
    asm("cvt.rna.tf32.f32 %0, %1;" : "=r"(u) : "f"(f));
    return __uint_as_float(u);
}
static __device__ __forceinline__ void ldmx4(uint32_t* r, uint32_t addr) {
    asm volatile("ldmatrix.sync.aligned.m8n8.x4.shared.b16 {%0,%1,%2,%3}, [%4];"
        : "=r"(r[0]), "=r"(r[1]), "=r"(r[2]), "=r"(r[3]) : "r"(addr));
}
static __device__ __forceinline__ void ldmx2(uint32_t* r, uint32_t addr) {
    asm volatile("ldmatrix.sync.aligned.m8n8.x2.shared.b16 {%0,%1}, [%2];"
        : "=r"(r[0]), "=r"(r[1]) : "r"(addr));
}
static __device__ __forceinline__ void mma_tf32(float* d, const uint32_t* a,
                                                const uint32_t* b) {
    asm volatile(
        "mma.sync.aligned.m16n8k8.row.col.f32.tf32.tf32.f32 "
        "{%0,%1,%2,%3}, {%4,%5,%6,%7}, {%8,%9}, {%0,%1,%2,%3};"
        : "+f"(d[0]), "+f"(d[1]), "+f"(d[2]), "+f"(d[3])
        : "r"(a[0]), "r"(a[1]), "r"(a[2]), "r"(a[3]), "r"(b[0]), "r"(b[1]));
}

__global__ void zero_out_kernel(float* out) {
    if (threadIdx.x < B_) out[threadIdx.x] = 0.0f;
}

__global__ __launch_bounds__(THREADS, 3)
void gnn_landmark_kernel(
    const float* __restrict__ x,       // (B,T,N,2)
    const float* __restrict__ W_enc,   // (2,F)
    const float* __restrict__ b_enc,   // (F)
    const float* __restrict__ W_gnn,   // (L,F,F)
    const float* __restrict__ b_gnn,   // (L,F)
    const float* __restrict__ gamma_,  // (L,F)
    const float* __restrict__ beta_,   // (L,F)
    const float* __restrict__ W1,      // (F,32)
    const float* __restrict__ b1,      // (32)
    const float* __restrict__ W2,      // (32,1)
    const float* __restrict__ b2,      // (1)
    float* __restrict__ out)           // (B)
{
    extern __shared__ char smc[];
    const uint32_t sb = s2u(smc);
    float* sh_h    = (float*)(smc + SM_H);
    float* sh_agg  = (float*)(smc + SM_AGG);
    float* sh_wt   = (float*)(smc + SM_WT);
    float* sh_pool = (float*)(smc + SM_POOL);
    float2* part   = (float2*)(smc + SM_PART);
    float2* musig  = (float2*)(smc + SM_MUSIG);

    const int tid  = threadIdx.x;
    const int lane = tid & 31;
    const int wp   = tid >> 5;
    const int nh   = wp & 1;              // feature half (32 cols)
    const int mgp  = wp >> 1;             // m-group 0..3
    const int mtb  = (mgp == 0) ? 0 : (mgp + 1);  // {0,1},{2},{3},{4}
    const int mtn  = (mgp == 0) ? 2 : 1;
    const int g    = lane >> 2;
    const int t    = lane & 3;

    // ---- encoder: h = x @ W_enc + b_enc
    const float* xb = x + (size_t)blockIdx.x * (N_ * 2);
    for (int idx = tid; idx < N_ * 16; idx += THREADS) {
        int n  = idx >> 4;
        int f4 = (idx & 15) << 2;
        float x0 = xb[2 * n];
        float x1 = xb[2 * n + 1];
        float4 w0 = __ldg((const float4*)(W_enc + f4));
        float4 w1 = __ldg((const float4*)(W_enc + F_ + f4));
        float4 be = __ldg((const float4*)(b_enc + f4));
        float4 h;
        h.x = fmaf(x0, w0.x, fmaf(x1, w1.x, be.x));
        h.y = fmaf(x0, w0.y, fmaf(x1, w1.y, be.y));
        h.z = fmaf(x0, w0.z, fmaf(x1, w1.z, be.z));
        h.w = fmaf(x0, w0.w, fmaf(x1, w1.w, be.w));
        *(float4*)(sh_h + n * HP + f4) = h;
    }
    __syncthreads();

    // ---- constant lane address bases
    uint32_t aAddr[2];
    #pragma unroll
    for (int i = 0; i < 2; ++i) {
        int mt  = mtb + i;
        int row = mt * 16 + ((lane >> 3) & 1) * 8 + (lane & 7);
        if (row >= N_) row = 0;                 // clamp: garbage rows
        aAddr[i] = sb + SM_AGG + (uint32_t)(row * ROWB + ((lane >> 4) & 1) * 16);
    }
    uint32_t bAddr[4];
    {
        int l4 = lane & 15;
        #pragma unroll
        for (int nt = 0; nt < 4; ++nt) {
            int n = nh * 32 + nt * 8 + (l4 & 7);
            bAddr[nt] = sb + SM_WT + (uint32_t)(n * ROWB + ((l4 >> 3) & 1) * 16);
        }
    }

    for (int l = 0; l < NLAYERS; ++l) {
        const float* Wl = W_gnn + l * (F_ * F_);

        // ---- stage W^T (rows = n, cols = k), PRE-CONVERTED tf32
        {
            int k = tid & 63, q = tid >> 6;       // q: 0..3 -> n block 16q
            const float* wr = Wl + k * F_ + q * 16;
            #pragma unroll
            for (int c = 0; c < 4; ++c) {
                float4 v = __ldg((const float4*)(wr + 4 * c));
                int n = q * 16 + 4 * c;
                sh_wt[(n + 0) * HP + k] = f2tf32f(v.x);
                sh_wt[(n + 1) * HP + k] = f2tf32f(v.y);
                sh_wt[(n + 2) * HP + k] = f2tf32f(v.z);
                sh_wt[(n + 3) * HP + k] = f2tf32f(v.w);
            }
        }
        // ---- stage agg row-major, PRE-CONVERTED tf32 (5-row strips)
        {
            int s = tid & 15, j = (tid >> 4) << 2;   // strip, float4 col
            float4 v[7];
            #pragma unroll
            for (int o = 0; o < 7; ++o) {
                int r = 5 * s - 1 + o;
                v[o] = ((unsigned)r < N_) ? *(const float4*)(sh_h + r * HP + j)
                                          : make_float4(0.f, 0.f, 0.f, 0.f);
            }
            #pragma unroll
            for (int o = 0; o < 5; ++o) {
                int r = 5 * s + o;
                if (r < N_) {
                    float4 a;
                    a.x = f2tf32f(v[o].x + v[o + 2].x);
                    a.y = f2tf32f(v[o].y + v[o + 2].y);
                    a.z = f2tf32f(v[o].z + v[o + 2].z);
                    a.w = f2tf32f(v[o].w + v[o + 2].w);
                    *(float4*)(sh_agg + r * HP + j) = a;
                }
            }
        }
        __syncthreads();

        // ---- warp GEMM: ldmatrix A + ldmatrix B, zero cvt in loop
        float acc[2][4][4];
        #pragma unroll
        for (int i = 0; i < 2; ++i)
            #pragma unroll
            for (int nt = 0; nt < 4; ++nt)
                #pragma unroll
                for (int q = 0; q < 4; ++q) acc[i][nt][q] = 0.f;

        #pragma unroll
        for (int ks = 0; ks < 8; ++ks) {
            const uint32_t koff = (uint32_t)(ks * 32);
            uint32_t b[4][2];
            #pragma unroll
            for (int nt = 0; nt < 4; ++nt)
                ldmx2(b[nt], bAddr[nt] + koff);
            #pragma unroll
            for (int i = 0; i < 2; ++i) {
                if (i < mtn) {
                    uint32_t a[4];
                    ldmx4(a, aAddr[i] + koff);
                    #pragma unroll
                    for (int nt = 0; nt < 4; ++nt)
                        mma_tf32(acc[i][nt], a, b[nt]);
                }
            }
        }

        // ---- epilogue: bias+relu, LN partials (32-col per warp), reduce, apply
        float2 bias[4];
        #pragma unroll
        for (int nt = 0; nt < 4; ++nt)
            bias[nt] = __ldg((const float2*)(b_gnn + l * F_ + nh * 32 + nt * 8 + 2 * t));

        #pragma unroll
        for (int i = 0; i < 2; ++i) {
            if (i < mtn) {
                int r0 = (mtb + i) * 16 + g;
                int r1 = r0 + 8;
                float s1a = 0.f, s2a = 0.f, s1b = 0.f, s2b = 0.f;
                #pragma unroll
                for (int nt = 0; nt < 4; ++nt) {
                    float z0 = fmaxf(acc[i][nt][0] + bias[nt].x, 0.f);
                    float z1 = fmaxf(acc[i][nt][1] + bias[nt].y, 0.f);
                    float z2 = fmaxf(acc[i][nt][2] + bias[nt].x, 0.f);
                    float z3 = fmaxf(acc[i][nt][3] + bias[nt].y, 0.f);
                    s1a += z0 + z1;  s2a += fmaf(z0, z0, z1 * z1);
                    s1b += z2 + z3;  s2b += fmaf(z2, z2, z3 * z3);
                }
                #pragma unroll
                for (int off = 1; off < 4; off <<= 1) {
                    s1a += __shfl_xor_sync(0xffffffffu, s1a, off);
                    s2a += __shfl_xor_sync(0xffffffffu, s2a, off);
                    s1b += __shfl_xor_sync(0xffffffffu, s1b, off);
                    s2b += __shfl_xor_sync(0xffffffffu, s2b, off);
                }
                if (t == 0) {
                    if (r0 < N_) part[r0 * 2 + nh] = make_float2(s1a, s2a);
                    if (r1 < N_) part[r1 * 2 + nh] = make_float2(s1b, s2b);
                }
            }
        }
        __syncthreads();

        if (tid < N_) {
            float2 p0 = part[tid * 2 + 0];
            float2 p1 = part[tid * 2 + 1];
            float s1 = p0.x + p1.x;
            float s2 = p0.y + p1.y;
            float mu  = s1 * (1.0f / F_);
            float var = s2 * (1.0f / F_) - mu * mu;
            musig[tid] = make_float2(mu, rsqrtf(var + 1e-5f));
        }
        __syncthreads();

        float2 gm[4], bt[4];
        #pragma unroll
        for (int nt = 0; nt < 4; ++nt) {
            int c = nh * 32 + nt * 8 + 2 * t;
            gm[nt] = __ldg((const float2*)(gamma_ + l * F_ + c));
            bt[nt] = __ldg((const float2*)(beta_ + l * F_ + c));
        }

        #pragma unroll
        for (int i = 0; i < 2; ++i) {
            if (i < mtn) {
                int r0 = (mtb + i) * 16 + g;
                int r1 = r0 + 8;
                if (r0 < N_) {
                    float2 ms = musig[r0];
                    #pragma unroll
                    for (int nt = 0; nt < 4; ++nt) {
                        int c = nh * 32 + nt * 8 + 2 * t;
                        float z0 = fmaxf(acc[i][nt][0] + bias[nt].x, 0.f);
                        float z1 = fmaxf(acc[i][nt][1] + bias[nt].y, 0.f);
                        float2* hp = (float2*)(sh_h + r0 * HP + c);
                        float2 h = *hp;
                        h.x += fmaf((z0 - ms.x) * ms.y, gm[nt].x, bt[nt].x);
                        h.y += fmaf((z1 - ms.x) * ms.y, gm[nt].y, bt[nt].y);
                        *hp = h;
                    }
                }
                if (r1 < N_) {
                    float2 ms = musig[r1];
                    #pragma unroll
                    for (int nt = 0; nt < 4; ++nt) {
                        int c = nh * 32 + nt * 8 + 2 * t;
                        float z2 = fmaxf(acc[i][nt][2] + bias[nt].x, 0.f);
                        float z3 = fmaxf(acc[i][nt][3] + bias[nt].y, 0.f);
                        float2* hp = (float2*)(sh_h + r1 * HP + c);
                        float2 h = *hp;
                        h.x += fmaf((z2 - ms.x) * ms.y, gm[nt].x, bt[nt].x);
                        h.y += fmaf((z3 - ms.x) * ms.y, gm[nt].y, bt[nt].y);
                        *hp = h;
                    }
                }
            }
        }
        __syncthreads();
    }

    // ---- pool over nodes ----
    if (tid < F_) {
        float s = 0.f;
        #pragma unroll
        for (int n = 0; n < N_; ++n) s += sh_h[n * HP + tid];
        sh_pool[tid] = s * (1.0f / N_);
    }
    __syncthreads();

    // ---- MLP head + mean over T ----
    if (tid < 32) {
        float a = __ldg(b1 + tid);
        #pragma unroll
        for (int f = 0; f < F_; ++f)
            a = fmaf(sh_pool[f], __ldg(W1 + f * 32 + tid), a);
        a = fmaxf(a, 0.f) * __ldg(W2 + tid);
        #pragma unroll
        for (int off = 16; off > 0; off >>= 1)
            a += __shfl_xor_sync(0xffffffffu, a, off);
        if (tid == 0) {
            float logit = a + __ldg(b2);
            atomicAdd(out + (blockIdx.x >> 8), logit * (1.0f / T_));
        }
    }
}

extern "C" void kernel_launch(void* const* d_in, const int* in_sizes, int n_in,
                              void* d_out, int out_size) {
    const float* x      = (const float*)d_in[0];   // landmarks_sequence
    // d_in[1] = adj (tridiagonal; structure hardcoded)
    const float* W_enc  = (const float*)d_in[2];
    const float* b_enc  = (const float*)d_in[3];
    const float* W_gnn  = (const float*)d_in[4];
    const float* b_gnn  = (const float*)d_in[5];
    const float* gamma_ = (const float*)d_in[6];
    const float* beta_  = (const float*)d_in[7];
    const float* W1     = (const float*)d_in[8];
    const float* b1     = (const float*)d_in[9];
    const float* W2     = (const float*)d_in[10];
    const float* b2     = (const float*)d_in[11];
    float* out = (float*)d_out;

    cudaFuncSetAttribute(gnn_landmark_kernel,
                         cudaFuncAttributeMaxDynamicSharedMemorySize, SM_TOTAL);

    zero_out_kernel<<<1, 32>>>(out);
    gnn_landmark_kernel<<<B_ * T_, THREADS, SM_TOTAL>>>(
        x, W_enc, b_enc, W_gnn, b_gnn, gamma_, beta_, W1, b1, W2, b2, out);
}

// round 17
// speedup vs baseline: 1.2963x; 1.2474x over previous
#include <cuda_runtime.h>
#include <cstdint>

// GNNLandmarkHead, tf32 mma.sync.m16n8k8 (base ISA), TWO samples per CTA.
// R10 fragment-order skeleton: A staged in fragment order (cvt at staging),
// B fragments staged once per layer (shared by both samples).
// Warps 0-3 -> sample 0, warps 4-7 -> sample 1; each warp owns ALL 5 m-tiles
// of its sample and a 16-feature n-slice (nw=wp&3). M padded to 80; rows >=68
// garbage, discarded in epilogue. 2 CTAs/SM.

#define B_  32
#define T_  256
#define N_  68
#define F_  64
#define HP  68
#define THREADS 256
#define NLAYERS 3

// SMEM byte offsets
#define SM_MUSIG 0        // 2 x 68 float2 = 1088
#define SM_PART  1088     // 2 x 68x4 float2 = 4352
#define SM_POOL  5440     // 2 x 64 f32 = 512
#define SM_AF    5952     // 2 x (5mt x 8ks x 32 x 16B) = 40960
#define SM_BF    46912    // 8ks x 8nt x 32 x 8B = 16384
#define SM_H     63296    // 2 x 68*68 f32 = 36992
#define SM_TOTAL 100288   // -> 2 CTAs/SM

#define AF_S 20480
#define H_S  4624         // floats per sample
#define PART_S 2176       // bytes
#define MUSIG_S 544       // bytes

static __device__ __forceinline__ uint32_t s2u(const void* p) {
    uint32_t a;
    asm("{ .reg .u64 t; cvta.to.shared.u64 t, %1; cvt.u32.u64 %0, t; }"
        : "=r"(a) : "l"(p));
    return a;
}
static __device__ __forceinline__ uint32_t f2tf32(float f) {
    uint32_t u;
    asm("cvt.rna.tf32.f32 %0, %1;" : "=r"(u) : "f"(f));
    return u;
}
static __device__ __forceinline__ void lds128(uint32_t* r, uint32_t a) {
    asm volatile("ld.shared.v4.b32 {%0,%1,%2,%3}, [%4];"
        : "=r"(r[0]), "=r"(r[1]), "=r"(r[2]), "=r"(r[3]) : "r"(a));
}
static __device__ __forceinline__ void lds64(uint32_t* r, uint32_t a) {
    asm volatile("ld.shared.v2.b32 {%0,%1}, [%2];"
        : "=r"(r[0]), "=r"(r[1]) : "r"(a));
}
static __device__ __forceinline__ void mma_tf32(float* d, const uint32_t* a,
                                                const uint32_t* b) {
    asm volatile(
        "mma.sync.aligned.m16n8k8.row.col.f32.tf32.tf32.f32 "
        "{%0,%1,%2,%3}, {%4,%5,%6,%7}, {%8,%9}, {%0,%1,%2,%3};"
        : "+f"(d[0]), "+f"(d[1]), "+f"(d[2]), "+f"(d[3])
        : "r"(a[0]), "r"(a[1]), "r"(a[2]), "r"(a[3]), "r"(b[0]), "r"(b[1]));
}

__global__ void zero_out_kernel(float* out) {
    if (threadIdx.x < B_) out[threadIdx.x] = 0.0f;
}

__global__ __launch_bounds__(THREADS, 2)
void gnn_landmark_kernel(
    const float* __restrict__ x,       // (B,T,N,2)
    const float* __restrict__ W_enc,   // (2,F)
    const float* __restrict__ b_enc,   // (F)
    const float* __restrict__ W_gnn,   // (L,F,F)
    const float* __restrict__ b_gnn,   // (L,F)
    const float* __restrict__ gamma_,  // (L,F)
    const float* __restrict__ beta_,   // (L,F)
    const float* __restrict__ W1,      // (F,32)
    const float* __restrict__ b1,      // (32)
    const float* __restrict__ W2,      // (32,1)
    const float* __restrict__ b2,      // (1)
    float* __restrict__ out)           // (B)
{
    extern __shared__ char smc[];
    const uint32_t sb = s2u(smc);

    const int tid  = threadIdx.x;
    const int lane = tid & 31;
    const int wp   = tid >> 5;
    const int smp  = wp >> 2;             // sample within CTA
    const int wl   = wp & 3;              // sample-local warp / n-slice
    const int l    = tid & 127;           // sample-local thread
    const int g    = lane >> 2;
    const int t    = lane & 3;

    float*  sh_h   = (float*)(smc + SM_H) + smp * H_S;
    float*  sh_pool= (float*)(smc + SM_POOL) + smp * 64;
    float2* part   = (float2*)(smc + SM_PART + smp * PART_S);
    float2* musig  = (float2*)(smc + SM_MUSIG + smp * MUSIG_S);
    const uint32_t afS = sb + SM_AF + (uint32_t)(smp * AF_S);

    const int si = 2 * blockIdx.x + smp;  // global sample index

    // ---- encoder: h = x @ W_enc + b_enc (128 threads per sample)
    const float* xb = x + (size_t)si * (N_ * 2);
    for (int idx = l; idx < N_ * 16; idx += 128) {
        int n  = idx >> 4;
        int f4 = (idx & 15) << 2;
        float x0 = xb[2 * n];
        float x1 = xb[2 * n + 1];
        float4 w0 = __ldg((const float4*)(W_enc + f4));
        float4 w1 = __ldg((const float4*)(W_enc + F_ + f4));
        float4 be = __ldg((const float4*)(b_enc + f4));
        float4 h;
        h.x = fmaf(x0, w0.x, fmaf(x1, w1.x, be.x));
        h.y = fmaf(x0, w0.y, fmaf(x1, w1.y, be.y));
        h.z = fmaf(x0, w0.z, fmaf(x1, w1.z, be.z));
        h.w = fmaf(x0, w0.w, fmaf(x1, w1.w, be.w));
        *(float4*)(sh_h + n * HP + f4) = h;
    }
    __syncthreads();

    for (int layer = 0; layer < NLAYERS; ++layer) {
        const float* Wl = W_gnn + layer * (F_ * F_);

        // ---- stage B fragments ONCE (all 8 warps): warp wp -> n-tile wp.
        // b0 = W[k][n], b1 = W[k+4][n]; k = ks*8+t, n = wp*8+g.
        {
            const int n = wp * 8 + g;
            #pragma unroll
            for (int ks = 0; ks < 8; ++ks) {
                int k = ks * 8 + t;
                uint32_t b0 = f2tf32(__ldg(Wl + k * F_ + n));
                uint32_t b1 = f2tf32(__ldg(Wl + (k + 4) * F_ + n));
                uint32_t addr = sb + SM_BF
                              + (uint32_t)(((ks * 8 + wp) * 32 + lane) * 8);
                asm volatile("st.shared.v2.b32 [%0], {%1,%2};"
                    :: "r"(addr), "r"(b0), "r"(b1));
            }
        }
        // ---- stage A fragments (per sample, 4 warps): warp wl -> ks=wl,wl+4.
        // a0=agg[m][k], a1=agg[m+8][k], a2=agg[m][k+4], a3=agg[m+8][k+4]
        #pragma unroll
        for (int kk = 0; kk < 2; ++kk) {
            const int ks = wl + 4 * kk;
            const int k0 = ks * 8 + t;
            #pragma unroll
            for (int mt = 0; mt < 5; ++mt) {
                int m = mt * 16 + g;
                int ra = m - 1, rb = m + 1, rc = m + 7, rd = m + 9;
                float va0 = ((unsigned)ra < N_) ? sh_h[ra * HP + k0] : 0.f;
                float vb0 = ((unsigned)rb < N_) ? sh_h[rb * HP + k0] : 0.f;
                float vc0 = ((unsigned)rc < N_) ? sh_h[rc * HP + k0] : 0.f;
                float vd0 = ((unsigned)rd < N_) ? sh_h[rd * HP + k0] : 0.f;
                float va1 = ((unsigned)ra < N_) ? sh_h[ra * HP + k0 + 4] : 0.f;
                float vb1 = ((unsigned)rb < N_) ? sh_h[rb * HP + k0 + 4] : 0.f;
                float vc1 = ((unsigned)rc < N_) ? sh_h[rc * HP + k0 + 4] : 0.f;
                float vd1 = ((unsigned)rd < N_) ? sh_h[rd * HP + k0 + 4] : 0.f;
                uint32_t a0 = f2tf32(va0 + vb0);
                uint32_t a1 = f2tf32(vc0 + vd0);
                uint32_t a2 = f2tf32(va1 + vb1);
                uint32_t a3 = f2tf32(vc1 + vd1);
                uint32_t addr = afS
                              + (uint32_t)(((mt * 8 + ks) * 32 + lane) * 16);
                asm volatile("st.shared.v4.b32 [%0], {%1,%2,%3,%4};"
                    :: "r"(addr), "r"(a0), "r"(a1), "r"(a2), "r"(a3));
            }
        }
        __syncthreads();

        // ---- warp GEMM: 5 m-tiles x 2 n-tiles, 8 k-steps (80 MMA, balanced)
        float acc[5][2][4];
        #pragma unroll
        for (int i = 0; i < 5; ++i)
            #pragma unroll
            for (int nt = 0; nt < 2; ++nt)
                #pragma unroll
                for (int q = 0; q < 4; ++q) acc[i][nt][q] = 0.f;

        const uint32_t afB = afS + (uint32_t)(lane * 16);
        const uint32_t bfB = sb + SM_BF + (uint32_t)(lane * 8);
        #pragma unroll
        for (int ks = 0; ks < 8; ++ks) {
            uint32_t b0[2], b1[2];
            lds64(b0, bfB + (uint32_t)((ks * 8 + 2 * wl) * 256));
            lds64(b1, bfB + (uint32_t)((ks * 8 + 2 * wl + 1) * 256));
            #pragma unroll
            for (int i = 0; i < 5; ++i) {
                uint32_t a[4];
                lds128(a, afB + (uint32_t)(((i * 8 + ks) * 512)));
                mma_tf32(acc[i][0], a, b0);
                mma_tf32(acc[i][1], a, b1);
            }
        }

        // ---- epilogue: bias+relu, LN partials, reduce, apply
        const int colb = wl * 16 + (t << 1);
        float2 bias0 = __ldg((const float2*)(b_gnn + layer * F_ + colb));
        float2 bias1 = __ldg((const float2*)(b_gnn + layer * F_ + colb + 8));

        #pragma unroll
        for (int i = 0; i < 5; ++i) {
            int r0 = i * 16 + g;
            int r1 = r0 + 8;
            float z00 = fmaxf(acc[i][0][0] + bias0.x, 0.f);
            float z01 = fmaxf(acc[i][0][1] + bias0.y, 0.f);
            float z02 = fmaxf(acc[i][1][0] + bias1.x, 0.f);
            float z03 = fmaxf(acc[i][1][1] + bias1.y, 0.f);
            float z10 = fmaxf(acc[i][0][2] + bias0.x, 0.f);
            float z11 = fmaxf(acc[i][0][3] + bias0.y, 0.f);
            float z12 = fmaxf(acc[i][1][2] + bias1.x, 0.f);
            float z13 = fmaxf(acc[i][1][3] + bias1.y, 0.f);
            float s1a = (z00 + z01) + (z02 + z03);
            float s2a = fmaf(z00, z00, z01 * z01) + fmaf(z02, z02, z03 * z03);
            float s1b = (z10 + z11) + (z12 + z13);
            float s2b = fmaf(z10, z10, z11 * z11) + fmaf(z12, z12, z13 * z13);
            #pragma unroll
            for (int off = 1; off < 4; off <<= 1) {
                s1a += __shfl_xor_sync(0xffffffffu, s1a, off);
                s2a += __shfl_xor_sync(0xffffffffu, s2a, off);
                s1b += __shfl_xor_sync(0xffffffffu, s1b, off);
                s2b += __shfl_xor_sync(0xffffffffu, s2b, off);
            }
            if (t == 0) {
                if (r0 < N_) part[r0 * 4 + wl] = make_float2(s1a, s2a);
                if (r1 < N_) part[r1 * 4 + wl] = make_float2(s1b, s2b);
            }
        }
        __syncthreads();

        if (l < N_) {
            float2 p0 = part[l * 4 + 0];
            float2 p1 = part[l * 4 + 1];
            float2 p2 = part[l * 4 + 2];
            float2 p3 = part[l * 4 + 3];
            float s1 = (p0.x + p1.x) + (p2.x + p3.x);
            float s2 = (p0.y + p1.y) + (p2.y + p3.y);
            float mu  = s1 * (1.0f / F_);
            float var = s2 * (1.0f / F_) - mu * mu;
            musig[l] = make_float2(mu, rsqrtf(var + 1e-5f));
        }
        __syncthreads();

        float2 g0 = __ldg((const float2*)(gamma_ + layer * F_ + colb));
        float2 g1 = __ldg((const float2*)(gamma_ + layer * F_ + colb + 8));
        float2 t0 = __ldg((const float2*)(beta_ + layer * F_ + colb));
        float2 t1 = __ldg((const float2*)(beta_ + layer * F_ + colb + 8));

        #pragma unroll
        for (int i = 0; i < 5; ++i) {
            int r0 = i * 16 + g;
            int r1 = r0 + 8;
            if (r0 < N_) {
                float2 ms = musig[r0];
                float z0 = fmaxf(acc[i][0][0] + bias0.x, 0.f);
                float z1 = fmaxf(acc[i][0][1] + bias0.y, 0.f);
                float z2 = fmaxf(acc[i][1][0] + bias1.x, 0.f);
                float z3 = fmaxf(acc[i][1][1] + bias1.y, 0.f);
                float2* h0p = (float2*)(sh_h + r0 * HP + colb);
                float2* h1p = (float2*)(sh_h + r0 * HP + colb + 8);
                float2 h0 = *h0p, h1 = *h1p;
                h0.x += fmaf((z0 - ms.x) * ms.y, g0.x, t0.x);
                h0.y += fmaf((z1 - ms.x) * ms.y, g0.y, t0.y);
                h1.x += fmaf((z2 - ms.x) * ms.y, g1.x, t1.x);
                h1.y += fmaf((z3 - ms.x) * ms.y, g1.y, t1.y);
                *h0p = h0; *h1p = h1;
            }
            if (r1 < N_) {
                float2 ms = musig[r1];
                float z0 = fmaxf(acc[i][0][2] + bias0.x, 0.f);
                float z1 = fmaxf(acc[i][0][3] + bias0.y, 0.f);
                float z2 = fmaxf(acc[i][1][2] + bias1.x, 0.f);
                float z3 = fmaxf(acc[i][1][3] + bias1.y, 0.f);
                float2* h0p = (float2*)(sh_h + r1 * HP + colb);
                float2* h1p = (float2*)(sh_h + r1 * HP + colb + 8);
                float2 h0 = *h0p, h1 = *h1p;
                h0.x += fmaf((z0 - ms.x) * ms.y, g0.x, t0.x);
                h0.y += fmaf((z1 - ms.x) * ms.y, g0.y, t0.y);
                h1.x += fmaf((z2 - ms.x) * ms.y, g1.x, t1.x);
                h1.y += fmaf((z3 - ms.x) * ms.y, g1.y, t1.y);
                *h0p = h0; *h1p = h1;
            }
        }
        __syncthreads();
    }

    // ---- pool over nodes (per sample) ----
    if (l < F_) {
        float s = 0.f;
        #pragma unroll
        for (int n = 0; n < N_; ++n) s += sh_h[n * HP + l];
        sh_pool[l] = s * (1.0f / N_);
    }
    __syncthreads();

    // ---- MLP head + mean over T (first warp of each sample) ----
    if (wl == 0) {
        float a = __ldg(b1 + lane);
        #pragma unroll
        for (int f = 0; f < F_; ++f)
            a = fmaf(sh_pool[f], __ldg(W1 + f * 32 + lane), a);
        a = fmaxf(a, 0.f) * __ldg(W2 + lane);
        #pragma unroll
        for (int off = 16; off > 0; off >>= 1)
            a += __shfl_xor_sync(0xffffffffu, a, off);
        if (lane == 0) {
            float logit = a + __ldg(b2);
            atomicAdd(out + (si >> 8), logit * (1.0f / T_));
        }
    }
}

extern "C" void kernel_launch(void* const* d_in, const int* in_sizes, int n_in,
                              void* d_out, int out_size) {
    const float* x      = (const float*)d_in[0];   // landmarks_sequence
    // d_in[1] = adj (tridiagonal; structure hardcoded)
    const float* W_enc  = (const float*)d_in[2];
    const float* b_enc  = (const float*)d_in[3];
    const float* W_gnn  = (const float*)d_in[4];
    const float* b_gnn  = (const float*)d_in[5];
    const float* gamma_ = (const float*)d_in[6];
    const float* beta_  = (const float*)d_in[7];
    const float* W1     = (const float*)d_in[8];
    const float* b1     = (const float*)d_in[9];
    const float* W2     = (const float*)d_in[10];
    const float* b2     = (const float*)d_in[11];
    float* out = (float*)d_out;

    cudaFuncSetAttribute(gnn_landmark_kernel,
                         cudaFuncAttributeMaxDynamicSharedMemorySize, SM_TOTAL);

    zero_out_kernel<<<1, 32>>>(out);
    gnn_landmark_kernel<<<(B_ * T_) / 2, THREADS, SM_TOTAL>>>(
        x, W_enc, b_enc, W_gnn, b_gnn, gamma_, beta_, W1, b1, W2, b2, out);
}